// round 11
// baseline (speedup 1.0000x reference)
#include <cuda_runtime.h>
#include <cuda_bf16.h>
#include <mma.h>
#include <math.h>

// ---------------------------------------------------------------------------
// BitNetAttention: B=2, S=2048, HID=1024, NH=16, HD=64
// Projections AND attention (scores + P*V) on bf16 tensor cores via wmma.
// Exact multi-plane bf16 splits keep everything equal to fp32 up to
// accumulation order. Softmax in fp32. (No inline asm / template decls /
// uint32_t -- bench pipeline constraints.)
// ---------------------------------------------------------------------------

#define Bsz   2
#define Ssz   2048
#define HID   1024
#define NH    16
#define HD    64
#define MROWS (Bsz * Ssz)
#define WELEM (HID * HID)
#define PLANE ((size_t)MROWS * HID)
#define SMEM_ATTN 92160

namespace wx = nvcuda::wmma;

__device__ double g_part[4][64];
__device__ float  g_scale[4];
__device__ __nv_bfloat16 g_wb[4 * WELEM];
__device__ __nv_bfloat16 g_pl[3 * MROWS * HID];
__device__ __nv_bfloat16 g_qpl[3 * MROWS * HID];
__device__ __nv_bfloat16 g_kpl[3 * MROWS * HID];
__device__ __nv_bfloat16 g_vpl[2 * MROWS * HID];
__device__ float  g_qkv[3 * MROWS * HID];
__device__ float  g_ctx[MROWS * HID];
__device__ float  g_cos[Ssz * 32];
__device__ float  g_sin[Ssz * 32];

// ------------------------- abssum partials ---------------------------------
__global__ __launch_bounds__(256) void k_abssum(const float* __restrict__ w0,
                                                const float* __restrict__ w1,
                                                const float* __restrict__ w2,
                                                const float* __restrict__ w3) {
    const int y = blockIdx.y;
    const float* w = (y == 0) ? w0 : (y == 1) ? w1 : (y == 2) ? w2 : w3;
    float acc = 0.f;
    const int n4 = WELEM / 4;
    for (int i = blockIdx.x * blockDim.x + threadIdx.x; i < n4; i += gridDim.x * blockDim.x) {
        float4 v = ((const float4*)w)[i];
        acc += fabsf(v.x) + fabsf(v.y) + fabsf(v.z) + fabsf(v.w);
    }
    for (int o = 16; o; o >>= 1) acc += __shfl_xor_sync(0xffffffffu, acc, o);
    __shared__ float red[8];
    if ((threadIdx.x & 31) == 0) red[threadIdx.x >> 5] = acc;
    __syncthreads();
    if (threadIdx.x < 8) {
        acc = red[threadIdx.x];
        for (int o = 4; o; o >>= 1) acc += __shfl_xor_sync(0xffu, acc, o);
        if (threadIdx.x == 0) g_part[y][blockIdx.x] = (double)acc;
    }
}

// exact 3-plane split of fp32 into bf16 planes
__global__ __launch_bounds__(256) void k_split(const float* __restrict__ x) {
    int i = blockIdx.x * blockDim.x + threadIdx.x;
    if (i >= (MROWS * HID) / 4) return;
    float4 v = ((const float4*)x)[i];
    float xs[4];
    xs[0] = v.x; xs[1] = v.y; xs[2] = v.z; xs[3] = v.w;
    unsigned int w0[2], w1[2], w2[2];
    #pragma unroll
    for (int pair = 0; pair < 2; pair++) {
        unsigned int a0 = 0, a1 = 0, a2 = 0;
        #pragma unroll
        for (int e = 0; e < 2; e++) {
            float xv = xs[pair * 2 + e];
            __nv_bfloat16 h0 = __float2bfloat16_rn(xv);
            float r1 = __fsub_rn(xv, __bfloat162float(h0));
            __nv_bfloat16 h1 = __float2bfloat16_rn(r1);
            float r2 = __fsub_rn(r1, __bfloat162float(h1));
            __nv_bfloat16 h2 = __float2bfloat16_rn(r2);
            a0 |= (unsigned int)__bfloat16_as_ushort(h0) << (16 * e);
            a1 |= (unsigned int)__bfloat16_as_ushort(h1) << (16 * e);
            a2 |= (unsigned int)__bfloat16_as_ushort(h2) << (16 * e);
        }
        w0[pair] = a0; w1[pair] = a1; w2[pair] = a2;
    }
    ((uint2*)(g_pl + 0 * PLANE))[i] = make_uint2(w0[0], w0[1]);
    ((uint2*)(g_pl + 1 * PLANE))[i] = make_uint2(w1[0], w1[1]);
    ((uint2*)(g_pl + 2 * PLANE))[i] = make_uint2(w2[0], w2[1]);
}

// quantize; absmean scale reduced from partials at block start
__global__ __launch_bounds__(256) void k_quant(const float* __restrict__ w0,
                                               const float* __restrict__ w1,
                                               const float* __restrict__ w2,
                                               const float* __restrict__ w3) {
    const int y = blockIdx.y;
    const float* w = (y == 0) ? w0 : (y == 1) ? w1 : (y == 2) ? w2 : w3;
    __nv_bfloat16* q = g_wb + (size_t)y * WELEM;
    __shared__ float s_sc;
    if (threadIdx.x < 32) {
        double d = g_part[y][threadIdx.x] + g_part[y][threadIdx.x + 32];
        for (int o = 16; o; o >>= 1) d += __shfl_xor_sync(0xffffffffu, d, o);
        if (threadIdx.x == 0) {
            float m = (float)(d * (1.0 / (double)WELEM)) + 1e-5f;
            s_sc = m;
            g_scale[y] = m;
        }
    }
    __syncthreads();
    const float sc = s_sc;
    const int n4 = WELEM / 4;
    for (int i = blockIdx.x * blockDim.x + threadIdx.x; i < n4; i += gridDim.x * blockDim.x) {
        float4 v = ((const float4*)w)[i];
        float r0 = fminf(1.f, fmaxf(-1.f, rintf(__fdiv_rn(v.x, sc))));
        float r1 = fminf(1.f, fmaxf(-1.f, rintf(__fdiv_rn(v.y, sc))));
        float r2 = fminf(1.f, fmaxf(-1.f, rintf(__fdiv_rn(v.z, sc))));
        float r3 = fminf(1.f, fmaxf(-1.f, rintf(__fdiv_rn(v.w, sc))));
        unsigned int lo = ((unsigned int)__bfloat16_as_ushort(__float2bfloat16_rn(r1)) << 16)
                        | (unsigned int)__bfloat16_as_ushort(__float2bfloat16_rn(r0));
        unsigned int hi = ((unsigned int)__bfloat16_as_ushort(__float2bfloat16_rn(r3)) << 16)
                        | (unsigned int)__bfloat16_as_ushort(__float2bfloat16_rn(r2));
        ((uint2*)q)[i] = make_uint2(lo, hi);
    }
}

// ------------------------- wmma bf16 GEMM, 3 planes ------------------------
__global__ __launch_bounds__(256) void k_bgemm3(const __nv_bfloat16* __restrict__ A,
                                                const __nv_bfloat16* __restrict__ B,
                                                float* __restrict__ C) {
    __shared__ __align__(16) __nv_bfloat16 sm[2][4][128 * 24];
    const int t = threadIdx.x;
    const int wid = t >> 5;
    const int wm = (wid >> 1) * 32;
    const int wn = (wid & 1) * 64;
    const int lrow = t >> 1;
    const int lcol = (t & 1) * 8;
    const __nv_bfloat16* ag = A + ((size_t)blockIdx.y * 128 + lrow) * HID + lcol;
    const __nv_bfloat16* bg = B + ((size_t)blockIdx.x * 128 + lrow) * HID + lcol;

    wx::fragment<wx::accumulator, 16, 16, 16, float> acc[2][4];
    #pragma unroll
    for (int i = 0; i < 2; i++)
        #pragma unroll
        for (int j = 0; j < 4; j++)
            wx::fill_fragment(acc[i][j], 0.0f);

    uint4 ra0 = *(const uint4*)(ag + 0 * PLANE);
    uint4 ra1 = *(const uint4*)(ag + 1 * PLANE);
    uint4 ra2 = *(const uint4*)(ag + 2 * PLANE);
    uint4 rb  = *(const uint4*)bg;
    *(uint4*)&sm[0][0][lrow * 24 + lcol] = ra0;
    *(uint4*)&sm[0][1][lrow * 24 + lcol] = ra1;
    *(uint4*)&sm[0][2][lrow * 24 + lcol] = ra2;
    *(uint4*)&sm[0][3][lrow * 24 + lcol] = rb;
    __syncthreads();

    #pragma unroll 1
    for (int it = 0; it < 64; ++it) {
        const int cur = it & 1;
        if (it < 63) {
            const int k0 = (it + 1) * 16;
            ra0 = *(const uint4*)(ag + 0 * PLANE + k0);
            ra1 = *(const uint4*)(ag + 1 * PLANE + k0);
            ra2 = *(const uint4*)(ag + 2 * PLANE + k0);
            rb  = *(const uint4*)(bg + k0);
        }
        wx::fragment<wx::matrix_b, 16, 16, 16, __nv_bfloat16, wx::col_major> bf[4];
        #pragma unroll
        for (int j = 0; j < 4; j++)
            wx::load_matrix_sync(bf[j], &sm[cur][3][(wn + 16 * j) * 24], 24);
        #pragma unroll
        for (int s = 0; s < 3; s++) {
            wx::fragment<wx::matrix_a, 16, 16, 16, __nv_bfloat16, wx::row_major> af[2];
            wx::load_matrix_sync(af[0], &sm[cur][s][(wm) * 24], 24);
            wx::load_matrix_sync(af[1], &sm[cur][s][(wm + 16) * 24], 24);
            #pragma unroll
            for (int i = 0; i < 2; i++)
                #pragma unroll
                for (int j = 0; j < 4; j++)
                    wx::mma_sync(acc[i][j], af[i], bf[j], acc[i][j]);
        }
        if (it < 63) {
            const int nxt = cur ^ 1;
            *(uint4*)&sm[nxt][0][lrow * 24 + lcol] = ra0;
            *(uint4*)&sm[nxt][1][lrow * 24 + lcol] = ra1;
            *(uint4*)&sm[nxt][2][lrow * 24 + lcol] = ra2;
            *(uint4*)&sm[nxt][3][lrow * 24 + lcol] = rb;
            __syncthreads();
        }
    }

    #pragma unroll
    for (int i = 0; i < 2; i++)
        #pragma unroll
        for (int j = 0; j < 4; j++) {
            float* cp = C + ((size_t)blockIdx.y * 128 + wm + 16 * i) * HID
                          + blockIdx.x * 128 + wn + 16 * j;
            wx::store_matrix_sync(cp, acc[i][j], HID, wx::mem_row_major);
        }
}

// Same with 2 planes (V and O projections).
__global__ __launch_bounds__(256) void k_bgemm2(const __nv_bfloat16* __restrict__ A,
                                                const __nv_bfloat16* __restrict__ B,
                                                float* __restrict__ C) {
    __shared__ __align__(16) __nv_bfloat16 sm[2][3][128 * 24];
    const int t = threadIdx.x;
    const int wid = t >> 5;
    const int wm = (wid >> 1) * 32;
    const int wn = (wid & 1) * 64;
    const int lrow = t >> 1;
    const int lcol = (t & 1) * 8;
    const __nv_bfloat16* ag = A + ((size_t)blockIdx.y * 128 + lrow) * HID + lcol;
    const __nv_bfloat16* bg = B + ((size_t)blockIdx.x * 128 + lrow) * HID + lcol;

    wx::fragment<wx::accumulator, 16, 16, 16, float> acc[2][4];
    #pragma unroll
    for (int i = 0; i < 2; i++)
        #pragma unroll
        for (int j = 0; j < 4; j++)
            wx::fill_fragment(acc[i][j], 0.0f);

    uint4 ra0 = *(const uint4*)(ag + 0 * PLANE);
    uint4 ra1 = *(const uint4*)(ag + 1 * PLANE);
    uint4 rb  = *(const uint4*)bg;
    *(uint4*)&sm[0][0][lrow * 24 + lcol] = ra0;
    *(uint4*)&sm[0][1][lrow * 24 + lcol] = ra1;
    *(uint4*)&sm[0][2][lrow * 24 + lcol] = rb;
    __syncthreads();

    #pragma unroll 1
    for (int it = 0; it < 64; ++it) {
        const int cur = it & 1;
        if (it < 63) {
            const int k0 = (it + 1) * 16;
            ra0 = *(const uint4*)(ag + 0 * PLANE + k0);
            ra1 = *(const uint4*)(ag + 1 * PLANE + k0);
            rb  = *(const uint4*)(bg + k0);
        }
        wx::fragment<wx::matrix_b, 16, 16, 16, __nv_bfloat16, wx::col_major> bf[4];
        #pragma unroll
        for (int j = 0; j < 4; j++)
            wx::load_matrix_sync(bf[j], &sm[cur][2][(wn + 16 * j) * 24], 24);
        #pragma unroll
        for (int s = 0; s < 2; s++) {
            wx::fragment<wx::matrix_a, 16, 16, 16, __nv_bfloat16, wx::row_major> af[2];
            wx::load_matrix_sync(af[0], &sm[cur][s][(wm) * 24], 24);
            wx::load_matrix_sync(af[1], &sm[cur][s][(wm + 16) * 24], 24);
            #pragma unroll
            for (int i = 0; i < 2; i++)
                #pragma unroll
                for (int j = 0; j < 4; j++)
                    wx::mma_sync(acc[i][j], af[i], bf[j], acc[i][j]);
        }
        if (it < 63) {
            const int nxt = cur ^ 1;
            *(uint4*)&sm[nxt][0][lrow * 24 + lcol] = ra0;
            *(uint4*)&sm[nxt][1][lrow * 24 + lcol] = ra1;
            *(uint4*)&sm[nxt][2][lrow * 24 + lcol] = rb;
            __syncthreads();
        }
    }

    #pragma unroll
    for (int i = 0; i < 2; i++)
        #pragma unroll
        for (int j = 0; j < 4; j++) {
            float* cp = C + ((size_t)blockIdx.y * 128 + wm + 16 * i) * HID
                          + blockIdx.x * 128 + wn + 16 * j;
            wx::store_matrix_sync(cp, acc[i][j], HID, wx::mem_row_major);
        }
}

// ------------------------- trig table --------------------------------------
__global__ __launch_bounds__(256) void k_trig() {
    int idx = blockIdx.x * blockDim.x + threadIdx.x;
    if (idx >= Ssz * 32) return;
    int pos = idx >> 5;
    int d2  = idx & 31;
    float e = (float)(2 * d2) / 64.0f;
    float t = (float)pow(10000.0, (double)e);
    float invf = __frcp_rn(t);
    float f = __fmul_rn((float)pos, invf);
    double sd, cd;
    sincos((double)f, &sd, &cd);
    g_cos[idx] = (float)cd;
    g_sin[idx] = (float)sd;
}

// ------------------------- RoPE + exact 3-plane split of q,k ----------------
__global__ __launch_bounds__(256) void k_rope(const int* __restrict__ pos_ids) {
    int idx = blockIdx.x * blockDim.x + threadIdx.x;
    if (idx >= MROWS * NH * 32) return;
    int m  = idx >> 9;
    int hp = idx & 511;
    int h  = hp >> 5;
    int d2 = hp & 31;
    int p = pos_ids[m];
    p = (p < 0) ? 0 : ((p >= Ssz) ? Ssz - 1 : p);
    float cs = g_cos[p * 32 + d2];
    float sn = g_sin[p * 32 + d2];
    size_t base = (size_t)m * HID + h * HD + d2;
    float q1 = g_qkv[base], q2 = g_qkv[base + 32];
    float k1 = g_qkv[PLANE + base], k2 = g_qkv[PLANE + base + 32];
    float vals[4];
    vals[0] = q1 * cs - q2 * sn;
    vals[1] = q2 * cs + q1 * sn;
    vals[2] = k1 * cs - k2 * sn;
    vals[3] = k2 * cs + k1 * sn;
    #pragma unroll
    for (int e = 0; e < 4; e++) {
        float xv = vals[e];
        __nv_bfloat16 h0 = __float2bfloat16_rn(xv);
        float r1 = __fsub_rn(xv, __bfloat162float(h0));
        __nv_bfloat16 h1 = __float2bfloat16_rn(r1);
        float r2 = __fsub_rn(r1, __bfloat162float(h1));
        __nv_bfloat16 h2 = __float2bfloat16_rn(r2);
        __nv_bfloat16* dst = (e < 2) ? g_qpl : g_kpl;
        size_t a = base + ((e & 1) ? 32 : 0);
        dst[0 * PLANE + a] = h0;
        dst[1 * PLANE + a] = h1;
        dst[2 * PLANE + a] = h2;
    }
}

// exact 2-plane split of V
__global__ __launch_bounds__(256) void k_vsplit() {
    int i = blockIdx.x * blockDim.x + threadIdx.x;
    if (i >= MROWS * HID) return;
    float xv = g_qkv[2 * PLANE + i];
    __nv_bfloat16 h0 = __float2bfloat16_rn(xv);
    float r1 = __fsub_rn(xv, __bfloat162float(h0));
    __nv_bfloat16 h1 = __float2bfloat16_rn(r1);
    g_vpl[0 * PLANE + i] = h0;
    g_vpl[1 * PLANE + i] = h1;
}

// ------------------------- attention (full wmma) ----------------------------
// Q tile 64, K tile 64. Dynamic smem layout (bytes):
//   qp  3x[64][72] bf16 @ 0      (27648)
//   kp  3x[64][72] bf16 @ 27648  (27648)   <- pp 2x[64][72] bf16 aliases here
//   vp  2x[64][72] bf16 @ 55296  (18432)
//   sc  [64][72] f32    @ 73728  (18432)   <- od aliases here
// total 92160
__global__ __launch_bounds__(256) void k_attn() {
    extern __shared__ __align__(16) char smb[];
    __nv_bfloat16* qp = (__nv_bfloat16*)(smb);
    __nv_bfloat16* kp = (__nv_bfloat16*)(smb + 27648);
    __nv_bfloat16* pp = (__nv_bfloat16*)(smb + 27648);
    __nv_bfloat16* vp = (__nv_bfloat16*)(smb + 55296);
    float* sc = (float*)(smb + 73728);
    float* od = (float*)(smb + 73728);

    const int tid = threadIdx.x;
    const int wid = tid >> 5;
    const int b = blockIdx.y >> 4;
    const int h = blockIdx.y & 15;
    const int q0 = blockIdx.x * 64;
    const size_t rowbase = (size_t)b * Ssz * HID + (size_t)h * HD;

    // load Q planes (rows 64, dims 64, pitch 72)
    for (int idx = tid; idx < 64 * 16; idx += 256) {
        int r = idx >> 4;
        int c4 = (idx & 15) * 4;
        size_t g = rowbase + (size_t)(q0 + r) * HID + c4;
        *(uint2*)(qp + 0 * 4608 + r * 72 + c4) = *(const uint2*)(g_qpl + 0 * PLANE + g);
        *(uint2*)(qp + 1 * 4608 + r * 72 + c4) = *(const uint2*)(g_qpl + 1 * PLANE + g);
        *(uint2*)(qp + 2 * 4608 + r * 72 + c4) = *(const uint2*)(g_qpl + 2 * PLANE + g);
    }

    const int ty = tid >> 4, tx = tid & 15;
    const int i0 = ty << 2;      // 4 query rows per thread (64 rows)
    const int j0 = tx << 2;      // 4 key cols per thread (64 keys)
    const int cj = tx << 2;      // 4 out dims per thread (64 dims)
    const int wr = wid >> 1;     // warp row tile (0..3)
    const int wc = wid & 1;      // warp col half (0..1)

    float m_i[4], l_i[4], o[4][4];
    #pragma unroll
    for (int i = 0; i < 4; i++) {
        m_i[i] = -3.0e38f; l_i[i] = 0.f;
        #pragma unroll
        for (int d = 0; d < 4; d++) o[i][d] = 0.f;
    }

    for (int kt = 0; kt < Ssz; kt += 64) {
        __syncthreads();   // S1: pp/od reads from previous tile are done
        for (int idx = tid; idx < 64 * 16; idx += 256) {
            int r = idx >> 4;
            int c4 = (idx & 15) * 4;
            size_t g = rowbase + (size_t)(kt + r) * HID + c4;
            *(uint2*)(kp + 0 * 4608 + r * 72 + c4) = *(const uint2*)(g_kpl + 0 * PLANE + g);
            *(uint2*)(kp + 1 * 4608 + r * 72 + c4) = *(const uint2*)(g_kpl + 1 * PLANE + g);
            *(uint2*)(kp + 2 * 4608 + r * 72 + c4) = *(const uint2*)(g_kpl + 2 * PLANE + g);
            *(uint2*)(vp + 0 * 4608 + r * 72 + c4) = *(const uint2*)(g_vpl + 0 * PLANE + g);
            *(uint2*)(vp + 1 * 4608 + r * 72 + c4) = *(const uint2*)(g_vpl + 1 * PLANE + g);
        }
        __syncthreads();   // S2

        // ----- scores: 6 exact plane terms -----
        wx::fragment<wx::accumulator, 16, 16, 16, float> sacc[2];
        wx::fill_fragment(sacc[0], 0.0f);
        wx::fill_fragment(sacc[1], 0.0f);
        #pragma unroll
        for (int si = 0; si < 3; si++) {
            wx::fragment<wx::matrix_a, 16, 16, 16, __nv_bfloat16, wx::row_major> af[4];
            #pragma unroll
            for (int kk = 0; kk < 4; kk++)
                wx::load_matrix_sync(af[kk], qp + si * 4608 + (wr * 16) * 72 + kk * 16, 72);
            #pragma unroll
            for (int sj = 0; sj < 3; sj++) {
                if (si + sj <= 2) {
                    #pragma unroll
                    for (int a = 0; a < 2; a++) {
                        #pragma unroll
                        for (int kk = 0; kk < 4; kk++) {
                            wx::fragment<wx::matrix_b, 16, 16, 16, __nv_bfloat16, wx::col_major> bfr;
                            wx::load_matrix_sync(bfr,
                                kp + sj * 4608 + (wc * 32 + a * 16) * 72 + kk * 16, 72);
                            wx::mma_sync(sacc[a], af[kk], bfr, sacc[a]);
                        }
                    }
                }
            }
        }
        #pragma unroll
        for (int a = 0; a < 2; a++)
            wx::store_matrix_sync(sc + (wr * 16) * 72 + wc * 32 + a * 16, sacc[a], 72,
                                  wx::mem_row_major);
        __syncthreads();   // S3

        // ----- softmax (fp32) + write 2-plane bf16 P; rescale O -----
        #pragma unroll
        for (int i = 0; i < 4; i++) {
            int row = i0 + i;
            float sv0 = sc[row * 72 + j0 + 0] * 0.125f;
            float sv1 = sc[row * 72 + j0 + 1] * 0.125f;
            float sv2 = sc[row * 72 + j0 + 2] * 0.125f;
            float sv3 = sc[row * 72 + j0 + 3] * 0.125f;
            float mx = fmaxf(fmaxf(sv0, sv1), fmaxf(sv2, sv3));
            #pragma unroll
            for (int off = 8; off; off >>= 1)
                mx = fmaxf(mx, __shfl_xor_sync(0xffffffffu, mx, off));
            float mnew = fmaxf(m_i[i], mx);
            float corr = __expf(m_i[i] - mnew);
            float p0 = __expf(sv0 - mnew);
            float p1 = __expf(sv1 - mnew);
            float p2 = __expf(sv2 - mnew);
            float p3 = __expf(sv3 - mnew);
            float rs = p0 + p1 + p2 + p3;
            #pragma unroll
            for (int off = 8; off; off >>= 1)
                rs += __shfl_xor_sync(0xffffffffu, rs, off);
            l_i[i] = l_i[i] * corr + rs;
            m_i[i] = mnew;
            #pragma unroll
            for (int d = 0; d < 4; d++) o[i][d] *= corr;
            float pv[4];
            pv[0] = p0; pv[1] = p1; pv[2] = p2; pv[3] = p3;
            #pragma unroll
            for (int j = 0; j < 4; j++) {
                __nv_bfloat16 hp0 = __float2bfloat16_rn(pv[j]);
                float rr = __fsub_rn(pv[j], __bfloat162float(hp0));
                __nv_bfloat16 hp1 = __float2bfloat16_rn(rr);
                pp[0 * 4608 + row * 72 + j0 + j] = hp0;
                pp[1 * 4608 + row * 72 + j0 + j] = hp1;
            }
        }
        __syncthreads();   // S4

        // ----- P @ V on tensor cores: p0v0 + p0v1 + p1v0 -----
        wx::fragment<wx::accumulator, 16, 16, 16, float> pacc[2];
        wx::fill_fragment(pacc[0], 0.0f);
        wx::fill_fragment(pacc[1], 0.0f);
        wx::fragment<wx::matrix_a, 16, 16, 16, __nv_bfloat16, wx::row_major> apf[2][4];
        #pragma unroll
        for (int tp = 0; tp < 2; tp++)
            #pragma unroll
            for (int kk = 0; kk < 4; kk++)
                wx::load_matrix_sync(apf[tp][kk], pp + tp * 4608 + (wr * 16) * 72 + kk * 16, 72);
        #pragma unroll
        for (int a = 0; a < 2; a++) {
            #pragma unroll
            for (int tp = 0; tp < 2; tp++) {
                #pragma unroll
                for (int tv = 0; tv < 2; tv++) {
                    if (tp + tv <= 1) {
                        #pragma unroll
                        for (int kk = 0; kk < 4; kk++) {
                            wx::fragment<wx::matrix_b, 16, 16, 16, __nv_bfloat16, wx::row_major> bfr;
                            wx::load_matrix_sync(bfr,
                                vp + tv * 4608 + (kk * 16) * 72 + wc * 32 + a * 16, 72);
                            wx::mma_sync(pacc[a], apf[tp][kk], bfr, pacc[a]);
                        }
                    }
                }
            }
        }
        #pragma unroll
        for (int a = 0; a < 2; a++)
            wx::store_matrix_sync(od + (wr * 16) * 72 + wc * 32 + a * 16, pacc[a], 72,
                                  wx::mem_row_major);
        __syncthreads();   // S5

        #pragma unroll
        for (int i = 0; i < 4; i++)
            #pragma unroll
            for (int d = 0; d < 4; d++)
                o[i][d] += od[(i0 + i) * 72 + cj + d];
    }

    #pragma unroll
    for (int i = 0; i < 4; i++) {
        float inv = 1.0f / l_i[i];
        float4 w = make_float4(o[i][0] * inv, o[i][1] * inv, o[i][2] * inv, o[i][3] * inv);
        *(float4*)(g_ctx + rowbase + (size_t)(q0 + i0 + i) * HID + cj) = w;
    }
}

// ------------------------- out_scale ---------------------------------------
__global__ void k_out_scale(const float* __restrict__ hss, float* __restrict__ out, int out_size) {
    if (out_size >= MROWS * HID + 1) {
        out[MROWS * HID] = (hss[0] * g_scale[2]) * g_scale[3];
    }
}

// ------------------------- launch ------------------------------------------
extern "C" void kernel_launch(void* const* d_in, const int* in_sizes, int n_in,
                              void* d_out, int out_size) {
    const float* hs  = (const float*)d_in[0];
    const float* hss = (const float*)d_in[1];
    const int*   pos = (const int*)d_in[2];
    const float* wq  = (const float*)d_in[3];
    const float* wk  = (const float*)d_in[4];
    const float* wv  = (const float*)d_in[5];
    const float* wo  = (const float*)d_in[6];
    float* out = (float*)d_out;

    __nv_bfloat16 *p_wb, *p_pl;
    float *p_qkv, *p_ctx;
    cudaGetSymbolAddress((void**)&p_wb,  g_wb);
    cudaGetSymbolAddress((void**)&p_pl,  g_pl);
    cudaGetSymbolAddress((void**)&p_qkv, g_qkv);
    cudaGetSymbolAddress((void**)&p_ctx, g_ctx);

    float* qf = p_qkv + 0 * PLANE;
    float* kf = p_qkv + 1 * PLANE;
    float* vf = p_qkv + 2 * PLANE;

    cudaFuncSetAttribute(k_attn, cudaFuncAttributeMaxDynamicSharedMemorySize, SMEM_ATTN);

    k_abssum<<<dim3(64, 4), 256>>>(wq, wk, wv, wo);
    k_split<<<(MROWS * HID / 4 + 255) / 256, 256>>>(hs);
    k_quant<<<dim3(64, 4), 256>>>(wq, wk, wv, wo);

    dim3 gproj(HID / 128, MROWS / 128);
    k_bgemm3<<<gproj, 256>>>(p_pl, p_wb + 0 * (size_t)WELEM, qf);
    k_bgemm3<<<gproj, 256>>>(p_pl, p_wb + 1 * (size_t)WELEM, kf);
    k_bgemm2<<<gproj, 256>>>(p_pl, p_wb + 2 * (size_t)WELEM, vf);

    k_trig<<<(Ssz * 32 + 255) / 256, 256>>>();
    k_rope<<<(MROWS * NH * 32 + 255) / 256, 256>>>(pos);
    k_vsplit<<<(MROWS * HID + 255) / 256, 256>>>();

    k_attn<<<dim3(Ssz / 64, Bsz * NH), 256, SMEM_ATTN>>>();

    k_split<<<(MROWS * HID / 4 + 255) / 256, 256>>>(p_ctx);
    k_bgemm2<<<gproj, 256>>>(p_pl, p_wb + 3 * (size_t)WELEM, out);

    k_out_scale<<<1, 1>>>(hss, out, out_size);
}

// round 12
// speedup vs baseline: 1.4010x; 1.4010x over previous
#include <cuda_runtime.h>
#include <cuda_bf16.h>
#include <mma.h>
#include <math.h>

// ---------------------------------------------------------------------------
// BitNetAttention: B=2, S=2048, HID=1024, NH=16, HD=64
// Projections AND attention (scores + P*V) on bf16 tensor cores via wmma.
// Exact multi-plane bf16 splits keep everything equal to fp32 up to
// accumulation order. Softmax fp32; P is single-plane bf16 (argmax-like
// softmax: p_max = 1 exactly, the rest < e^-50). (No inline asm / template
// decls / uint32_t -- bench pipeline constraints.)
// ---------------------------------------------------------------------------

#define Bsz   2
#define Ssz   2048
#define HID   1024
#define NH    16
#define HD    64
#define MROWS (Bsz * Ssz)
#define WELEM (HID * HID)
#define PLANE ((size_t)MROWS * HID)
#define SMEM_ATTN 92160

namespace wx = nvcuda::wmma;

__device__ double g_part[4][64];
__device__ float  g_scale[4];
__device__ __nv_bfloat16 g_wb[4 * WELEM];
__device__ __nv_bfloat16 g_pl[3 * MROWS * HID];
__device__ __nv_bfloat16 g_qpl[3 * MROWS * HID];
__device__ __nv_bfloat16 g_kpl[3 * MROWS * HID];
__device__ __nv_bfloat16 g_vpl[2 * MROWS * HID];
__device__ float  g_qkv[3 * MROWS * HID];
__device__ float  g_ctx[MROWS * HID];
__device__ float  g_cos[Ssz * 32];
__device__ float  g_sin[Ssz * 32];

// ------------------------- abssum partials ---------------------------------
__global__ __launch_bounds__(256) void k_abssum(const float* __restrict__ w0,
                                                const float* __restrict__ w1,
                                                const float* __restrict__ w2,
                                                const float* __restrict__ w3) {
    const int y = blockIdx.y;
    const float* w = (y == 0) ? w0 : (y == 1) ? w1 : (y == 2) ? w2 : w3;
    float acc = 0.f;
    const int n4 = WELEM / 4;
    for (int i = blockIdx.x * blockDim.x + threadIdx.x; i < n4; i += gridDim.x * blockDim.x) {
        float4 v = ((const float4*)w)[i];
        acc += fabsf(v.x) + fabsf(v.y) + fabsf(v.z) + fabsf(v.w);
    }
    for (int o = 16; o; o >>= 1) acc += __shfl_xor_sync(0xffffffffu, acc, o);
    __shared__ float red[8];
    if ((threadIdx.x & 31) == 0) red[threadIdx.x >> 5] = acc;
    __syncthreads();
    if (threadIdx.x < 8) {
        acc = red[threadIdx.x];
        for (int o = 4; o; o >>= 1) acc += __shfl_xor_sync(0xffu, acc, o);
        if (threadIdx.x == 0) g_part[y][blockIdx.x] = (double)acc;
    }
}

// exact 3-plane split of fp32 into bf16 planes
__global__ __launch_bounds__(256) void k_split(const float* __restrict__ x) {
    int i = blockIdx.x * blockDim.x + threadIdx.x;
    if (i >= (MROWS * HID) / 4) return;
    float4 v = ((const float4*)x)[i];
    float xs[4];
    xs[0] = v.x; xs[1] = v.y; xs[2] = v.z; xs[3] = v.w;
    unsigned int w0[2], w1[2], w2[2];
    #pragma unroll
    for (int pair = 0; pair < 2; pair++) {
        unsigned int a0 = 0, a1 = 0, a2 = 0;
        #pragma unroll
        for (int e = 0; e < 2; e++) {
            float xv = xs[pair * 2 + e];
            __nv_bfloat16 h0 = __float2bfloat16_rn(xv);
            float r1 = __fsub_rn(xv, __bfloat162float(h0));
            __nv_bfloat16 h1 = __float2bfloat16_rn(r1);
            float r2 = __fsub_rn(r1, __bfloat162float(h1));
            __nv_bfloat16 h2 = __float2bfloat16_rn(r2);
            a0 |= (unsigned int)__bfloat16_as_ushort(h0) << (16 * e);
            a1 |= (unsigned int)__bfloat16_as_ushort(h1) << (16 * e);
            a2 |= (unsigned int)__bfloat16_as_ushort(h2) << (16 * e);
        }
        w0[pair] = a0; w1[pair] = a1; w2[pair] = a2;
    }
    ((uint2*)(g_pl + 0 * PLANE))[i] = make_uint2(w0[0], w0[1]);
    ((uint2*)(g_pl + 1 * PLANE))[i] = make_uint2(w1[0], w1[1]);
    ((uint2*)(g_pl + 2 * PLANE))[i] = make_uint2(w2[0], w2[1]);
}

// quantize; absmean scale reduced from partials at block start
__global__ __launch_bounds__(256) void k_quant(const float* __restrict__ w0,
                                               const float* __restrict__ w1,
                                               const float* __restrict__ w2,
                                               const float* __restrict__ w3) {
    const int y = blockIdx.y;
    const float* w = (y == 0) ? w0 : (y == 1) ? w1 : (y == 2) ? w2 : w3;
    __nv_bfloat16* q = g_wb + (size_t)y * WELEM;
    __shared__ float s_sc;
    if (threadIdx.x < 32) {
        double d = g_part[y][threadIdx.x] + g_part[y][threadIdx.x + 32];
        for (int o = 16; o; o >>= 1) d += __shfl_xor_sync(0xffffffffu, d, o);
        if (threadIdx.x == 0) {
            float m = (float)(d * (1.0 / (double)WELEM)) + 1e-5f;
            s_sc = m;
            g_scale[y] = m;
        }
    }
    __syncthreads();
    const float sc = s_sc;
    const int n4 = WELEM / 4;
    for (int i = blockIdx.x * blockDim.x + threadIdx.x; i < n4; i += gridDim.x * blockDim.x) {
        float4 v = ((const float4*)w)[i];
        float r0 = fminf(1.f, fmaxf(-1.f, rintf(__fdiv_rn(v.x, sc))));
        float r1 = fminf(1.f, fmaxf(-1.f, rintf(__fdiv_rn(v.y, sc))));
        float r2 = fminf(1.f, fmaxf(-1.f, rintf(__fdiv_rn(v.z, sc))));
        float r3 = fminf(1.f, fmaxf(-1.f, rintf(__fdiv_rn(v.w, sc))));
        unsigned int lo = ((unsigned int)__bfloat16_as_ushort(__float2bfloat16_rn(r1)) << 16)
                        | (unsigned int)__bfloat16_as_ushort(__float2bfloat16_rn(r0));
        unsigned int hi = ((unsigned int)__bfloat16_as_ushort(__float2bfloat16_rn(r3)) << 16)
                        | (unsigned int)__bfloat16_as_ushort(__float2bfloat16_rn(r2));
        ((uint2*)q)[i] = make_uint2(lo, hi);
    }
}

// ------------------------- wmma bf16 GEMM, 3 planes ------------------------
__global__ __launch_bounds__(256) void k_bgemm3(const __nv_bfloat16* __restrict__ A,
                                                const __nv_bfloat16* __restrict__ B,
                                                float* __restrict__ C) {
    __shared__ __align__(16) __nv_bfloat16 sm[2][4][128 * 24];
    const int t = threadIdx.x;
    const int wid = t >> 5;
    const int wm = (wid >> 1) * 32;
    const int wn = (wid & 1) * 64;
    const int lrow = t >> 1;
    const int lcol = (t & 1) * 8;
    const __nv_bfloat16* ag = A + ((size_t)blockIdx.y * 128 + lrow) * HID + lcol;
    const __nv_bfloat16* bg = B + ((size_t)blockIdx.x * 128 + lrow) * HID + lcol;

    wx::fragment<wx::accumulator, 16, 16, 16, float> acc[2][4];
    #pragma unroll
    for (int i = 0; i < 2; i++)
        #pragma unroll
        for (int j = 0; j < 4; j++)
            wx::fill_fragment(acc[i][j], 0.0f);

    uint4 ra0 = *(const uint4*)(ag + 0 * PLANE);
    uint4 ra1 = *(const uint4*)(ag + 1 * PLANE);
    uint4 ra2 = *(const uint4*)(ag + 2 * PLANE);
    uint4 rb  = *(const uint4*)bg;
    *(uint4*)&sm[0][0][lrow * 24 + lcol] = ra0;
    *(uint4*)&sm[0][1][lrow * 24 + lcol] = ra1;
    *(uint4*)&sm[0][2][lrow * 24 + lcol] = ra2;
    *(uint4*)&sm[0][3][lrow * 24 + lcol] = rb;
    __syncthreads();

    #pragma unroll 1
    for (int it = 0; it < 64; ++it) {
        const int cur = it & 1;
        if (it < 63) {
            const int k0 = (it + 1) * 16;
            ra0 = *(const uint4*)(ag + 0 * PLANE + k0);
            ra1 = *(const uint4*)(ag + 1 * PLANE + k0);
            ra2 = *(const uint4*)(ag + 2 * PLANE + k0);
            rb  = *(const uint4*)(bg + k0);
        }
        wx::fragment<wx::matrix_b, 16, 16, 16, __nv_bfloat16, wx::col_major> bf[4];
        #pragma unroll
        for (int j = 0; j < 4; j++)
            wx::load_matrix_sync(bf[j], &sm[cur][3][(wn + 16 * j) * 24], 24);
        #pragma unroll
        for (int s = 0; s < 3; s++) {
            wx::fragment<wx::matrix_a, 16, 16, 16, __nv_bfloat16, wx::row_major> af[2];
            wx::load_matrix_sync(af[0], &sm[cur][s][(wm) * 24], 24);
            wx::load_matrix_sync(af[1], &sm[cur][s][(wm + 16) * 24], 24);
            #pragma unroll
            for (int i = 0; i < 2; i++)
                #pragma unroll
                for (int j = 0; j < 4; j++)
                    wx::mma_sync(acc[i][j], af[i], bf[j], acc[i][j]);
        }
        if (it < 63) {
            const int nxt = cur ^ 1;
            *(uint4*)&sm[nxt][0][lrow * 24 + lcol] = ra0;
            *(uint4*)&sm[nxt][1][lrow * 24 + lcol] = ra1;
            *(uint4*)&sm[nxt][2][lrow * 24 + lcol] = ra2;
            *(uint4*)&sm[nxt][3][lrow * 24 + lcol] = rb;
            __syncthreads();
        }
    }

    #pragma unroll
    for (int i = 0; i < 2; i++)
        #pragma unroll
        for (int j = 0; j < 4; j++) {
            float* cp = C + ((size_t)blockIdx.y * 128 + wm + 16 * i) * HID
                          + blockIdx.x * 128 + wn + 16 * j;
            wx::store_matrix_sync(cp, acc[i][j], HID, wx::mem_row_major);
        }
}

// Same with 2 planes (V and O projections).
__global__ __launch_bounds__(256) void k_bgemm2(const __nv_bfloat16* __restrict__ A,
                                                const __nv_bfloat16* __restrict__ B,
                                                float* __restrict__ C) {
    __shared__ __align__(16) __nv_bfloat16 sm[2][3][128 * 24];
    const int t = threadIdx.x;
    const int wid = t >> 5;
    const int wm = (wid >> 1) * 32;
    const int wn = (wid & 1) * 64;
    const int lrow = t >> 1;
    const int lcol = (t & 1) * 8;
    const __nv_bfloat16* ag = A + ((size_t)blockIdx.y * 128 + lrow) * HID + lcol;
    const __nv_bfloat16* bg = B + ((size_t)blockIdx.x * 128 + lrow) * HID + lcol;

    wx::fragment<wx::accumulator, 16, 16, 16, float> acc[2][4];
    #pragma unroll
    for (int i = 0; i < 2; i++)
        #pragma unroll
        for (int j = 0; j < 4; j++)
            wx::fill_fragment(acc[i][j], 0.0f);

    uint4 ra0 = *(const uint4*)(ag + 0 * PLANE);
    uint4 ra1 = *(const uint4*)(ag + 1 * PLANE);
    uint4 rb  = *(const uint4*)bg;
    *(uint4*)&sm[0][0][lrow * 24 + lcol] = ra0;
    *(uint4*)&sm[0][1][lrow * 24 + lcol] = ra1;
    *(uint4*)&sm[0][2][lrow * 24 + lcol] = rb;
    __syncthreads();

    #pragma unroll 1
    for (int it = 0; it < 64; ++it) {
        const int cur = it & 1;
        if (it < 63) {
            const int k0 = (it + 1) * 16;
            ra0 = *(const uint4*)(ag + 0 * PLANE + k0);
            ra1 = *(const uint4*)(ag + 1 * PLANE + k0);
            rb  = *(const uint4*)(bg + k0);
        }
        wx::fragment<wx::matrix_b, 16, 16, 16, __nv_bfloat16, wx::col_major> bf[4];
        #pragma unroll
        for (int j = 0; j < 4; j++)
            wx::load_matrix_sync(bf[j], &sm[cur][2][(wn + 16 * j) * 24], 24);
        #pragma unroll
        for (int s = 0; s < 2; s++) {
            wx::fragment<wx::matrix_a, 16, 16, 16, __nv_bfloat16, wx::row_major> af[2];
            wx::load_matrix_sync(af[0], &sm[cur][s][(wm) * 24], 24);
            wx::load_matrix_sync(af[1], &sm[cur][s][(wm + 16) * 24], 24);
            #pragma unroll
            for (int i = 0; i < 2; i++)
                #pragma unroll
                for (int j = 0; j < 4; j++)
                    wx::mma_sync(acc[i][j], af[i], bf[j], acc[i][j]);
        }
        if (it < 63) {
            const int nxt = cur ^ 1;
            *(uint4*)&sm[nxt][0][lrow * 24 + lcol] = ra0;
            *(uint4*)&sm[nxt][1][lrow * 24 + lcol] = ra1;
            *(uint4*)&sm[nxt][2][lrow * 24 + lcol] = rb;
            __syncthreads();
        }
    }

    #pragma unroll
    for (int i = 0; i < 2; i++)
        #pragma unroll
        for (int j = 0; j < 4; j++) {
            float* cp = C + ((size_t)blockIdx.y * 128 + wm + 16 * i) * HID
                          + blockIdx.x * 128 + wn + 16 * j;
            wx::store_matrix_sync(cp, acc[i][j], HID, wx::mem_row_major);
        }
}

// ------------------------- trig table --------------------------------------
__global__ __launch_bounds__(256) void k_trig() {
    int idx = blockIdx.x * blockDim.x + threadIdx.x;
    if (idx >= Ssz * 32) return;
    int pos = idx >> 5;
    int d2  = idx & 31;
    float e = (float)(2 * d2) / 64.0f;
    float t = (float)pow(10000.0, (double)e);
    float invf = __frcp_rn(t);
    float f = __fmul_rn((float)pos, invf);
    double sd, cd;
    sincos((double)f, &sd, &cd);
    g_cos[idx] = (float)cd;
    g_sin[idx] = (float)sd;
}

// ------------------------- RoPE + exact 3-plane split of q,k ----------------
__global__ __launch_bounds__(256) void k_rope(const int* __restrict__ pos_ids) {
    int idx = blockIdx.x * blockDim.x + threadIdx.x;
    if (idx >= MROWS * NH * 32) return;
    int m  = idx >> 9;
    int hp = idx & 511;
    int h  = hp >> 5;
    int d2 = hp & 31;
    int p = pos_ids[m];
    p = (p < 0) ? 0 : ((p >= Ssz) ? Ssz - 1 : p);
    float cs = g_cos[p * 32 + d2];
    float sn = g_sin[p * 32 + d2];
    size_t base = (size_t)m * HID + h * HD + d2;
    float q1 = g_qkv[base], q2 = g_qkv[base + 32];
    float k1 = g_qkv[PLANE + base], k2 = g_qkv[PLANE + base + 32];
    float vals[4];
    vals[0] = q1 * cs - q2 * sn;
    vals[1] = q2 * cs + q1 * sn;
    vals[2] = k1 * cs - k2 * sn;
    vals[3] = k2 * cs + k1 * sn;
    #pragma unroll
    for (int e = 0; e < 4; e++) {
        float xv = vals[e];
        __nv_bfloat16 h0 = __float2bfloat16_rn(xv);
        float r1 = __fsub_rn(xv, __bfloat162float(h0));
        __nv_bfloat16 h1 = __float2bfloat16_rn(r1);
        float r2 = __fsub_rn(r1, __bfloat162float(h1));
        __nv_bfloat16 h2 = __float2bfloat16_rn(r2);
        __nv_bfloat16* dst = (e < 2) ? g_qpl : g_kpl;
        size_t a = base + ((e & 1) ? 32 : 0);
        dst[0 * PLANE + a] = h0;
        dst[1 * PLANE + a] = h1;
        dst[2 * PLANE + a] = h2;
    }
}

// exact 2-plane split of V
__global__ __launch_bounds__(256) void k_vsplit() {
    int i = blockIdx.x * blockDim.x + threadIdx.x;
    if (i >= MROWS * HID) return;
    float xv = g_qkv[2 * PLANE + i];
    __nv_bfloat16 h0 = __float2bfloat16_rn(xv);
    float r1 = __fsub_rn(xv, __bfloat162float(h0));
    __nv_bfloat16 h1 = __float2bfloat16_rn(r1);
    g_vpl[0 * PLANE + i] = h0;
    g_vpl[1 * PLANE + i] = h1;
}

// ------------------------- attention (full wmma) ----------------------------
// Q tile 64, K tile 64. Dynamic smem layout (bytes):
//   qp  3x[64][72] bf16 @ 0      (27648)
//   kp  3x[64][72] bf16 @ 27648  (27648)   <- pp 1x[64][72] bf16 aliases here
//   vp  2x[64][72] bf16 @ 55296  (18432)
//   sc  [64][72] f32    @ 73728  (18432)   <- od aliases here
// total 92160
__global__ __launch_bounds__(256, 2) void k_attn() {
    extern __shared__ __align__(16) char smb[];
    __nv_bfloat16* qp = (__nv_bfloat16*)(smb);
    __nv_bfloat16* kp = (__nv_bfloat16*)(smb + 27648);
    __nv_bfloat16* pp = (__nv_bfloat16*)(smb + 27648);
    __nv_bfloat16* vp = (__nv_bfloat16*)(smb + 55296);
    float* sc = (float*)(smb + 73728);
    float* od = (float*)(smb + 73728);

    const int tid = threadIdx.x;
    const int wid = tid >> 5;
    const int b = blockIdx.y >> 4;
    const int h = blockIdx.y & 15;
    const int q0 = blockIdx.x * 64;
    const size_t rowbase = (size_t)b * Ssz * HID + (size_t)h * HD;

    // load Q planes (rows 64, dims 64, pitch 72)
    for (int idx = tid; idx < 64 * 16; idx += 256) {
        int r = idx >> 4;
        int c4 = (idx & 15) * 4;
        size_t g = rowbase + (size_t)(q0 + r) * HID + c4;
        *(uint2*)(qp + 0 * 4608 + r * 72 + c4) = *(const uint2*)(g_qpl + 0 * PLANE + g);
        *(uint2*)(qp + 1 * 4608 + r * 72 + c4) = *(const uint2*)(g_qpl + 1 * PLANE + g);
        *(uint2*)(qp + 2 * 4608 + r * 72 + c4) = *(const uint2*)(g_qpl + 2 * PLANE + g);
    }

    const int ty = tid >> 4, tx = tid & 15;
    const int i0 = ty << 2;      // 4 query rows per thread
    const int j0 = tx << 2;      // 4 key cols per thread
    const int cj = tx << 2;      // 4 out dims per thread
    const int wr = wid >> 1;     // warp row tile (0..3)
    const int wc = wid & 1;      // warp col half (0..1)

    float m_i[4], l_i[4], o[4][4];
    #pragma unroll
    for (int i = 0; i < 4; i++) {
        m_i[i] = -3.0e38f; l_i[i] = 0.f;
        #pragma unroll
        for (int d = 0; d < 4; d++) o[i][d] = 0.f;
    }

    for (int kt = 0; kt < Ssz; kt += 64) {
        __syncthreads();   // S1: pp/od reads from previous tile are done
        for (int idx = tid; idx < 64 * 16; idx += 256) {
            int r = idx >> 4;
            int c4 = (idx & 15) * 4;
            size_t g = rowbase + (size_t)(kt + r) * HID + c4;
            *(uint2*)(kp + 0 * 4608 + r * 72 + c4) = *(const uint2*)(g_kpl + 0 * PLANE + g);
            *(uint2*)(kp + 1 * 4608 + r * 72 + c4) = *(const uint2*)(g_kpl + 1 * PLANE + g);
            *(uint2*)(kp + 2 * 4608 + r * 72 + c4) = *(const uint2*)(g_kpl + 2 * PLANE + g);
            *(uint2*)(vp + 0 * 4608 + r * 72 + c4) = *(const uint2*)(g_vpl + 0 * PLANE + g);
            *(uint2*)(vp + 1 * 4608 + r * 72 + c4) = *(const uint2*)(g_vpl + 1 * PLANE + g);
        }
        __syncthreads();   // S2

        // ----- scores: 6 exact plane terms; each fragment loaded once -----
        wx::fragment<wx::accumulator, 16, 16, 16, float> sacc[2];
        wx::fill_fragment(sacc[0], 0.0f);
        wx::fill_fragment(sacc[1], 0.0f);
        #pragma unroll
        for (int kk = 0; kk < 4; kk++) {
            wx::fragment<wx::matrix_a, 16, 16, 16, __nv_bfloat16, wx::row_major> af[3];
            #pragma unroll
            for (int si = 0; si < 3; si++)
                wx::load_matrix_sync(af[si], qp + si * 4608 + (wr * 16) * 72 + kk * 16, 72);
            #pragma unroll
            for (int a = 0; a < 2; a++) {
                #pragma unroll
                for (int sj = 0; sj < 3; sj++) {
                    wx::fragment<wx::matrix_b, 16, 16, 16, __nv_bfloat16, wx::col_major> bfr;
                    wx::load_matrix_sync(bfr,
                        kp + sj * 4608 + (wc * 32 + a * 16) * 72 + kk * 16, 72);
                    #pragma unroll
                    for (int si = 0; si < 3; si++)
                        if (si + sj <= 2)
                            wx::mma_sync(sacc[a], af[si], bfr, sacc[a]);
                }
            }
        }
        #pragma unroll
        for (int a = 0; a < 2; a++)
            wx::store_matrix_sync(sc + (wr * 16) * 72 + wc * 32 + a * 16, sacc[a], 72,
                                  wx::mem_row_major);
        __syncthreads();   // S3

        // ----- softmax (fp32), write single-plane bf16 P (packed stores) -----
        #pragma unroll
        for (int i = 0; i < 4; i++) {
            int row = i0 + i;
            float sv0 = sc[row * 72 + j0 + 0] * 0.125f;
            float sv1 = sc[row * 72 + j0 + 1] * 0.125f;
            float sv2 = sc[row * 72 + j0 + 2] * 0.125f;
            float sv3 = sc[row * 72 + j0 + 3] * 0.125f;
            float mx = fmaxf(fmaxf(sv0, sv1), fmaxf(sv2, sv3));
            #pragma unroll
            for (int off = 8; off; off >>= 1)
                mx = fmaxf(mx, __shfl_xor_sync(0xffffffffu, mx, off));
            float mnew = fmaxf(m_i[i], mx);
            float corr = __expf(m_i[i] - mnew);
            float p0 = __expf(sv0 - mnew);
            float p1 = __expf(sv1 - mnew);
            float p2 = __expf(sv2 - mnew);
            float p3 = __expf(sv3 - mnew);
            float rs = p0 + p1 + p2 + p3;
            #pragma unroll
            for (int off = 8; off; off >>= 1)
                rs += __shfl_xor_sync(0xffffffffu, rs, off);
            l_i[i] = l_i[i] * corr + rs;
            m_i[i] = mnew;
            #pragma unroll
            for (int d = 0; d < 4; d++) o[i][d] *= corr;
            unsigned int lo = ((unsigned int)__bfloat16_as_ushort(__float2bfloat16_rn(p1)) << 16)
                            | (unsigned int)__bfloat16_as_ushort(__float2bfloat16_rn(p0));
            unsigned int hi = ((unsigned int)__bfloat16_as_ushort(__float2bfloat16_rn(p3)) << 16)
                            | (unsigned int)__bfloat16_as_ushort(__float2bfloat16_rn(p2));
            *(unsigned int*)(pp + row * 72 + j0)     = lo;
            *(unsigned int*)(pp + row * 72 + j0 + 2) = hi;
        }
        __syncthreads();   // S4

        // ----- P @ V on tensor cores: P * (V0 + V1); fragments loaded once -----
        wx::fragment<wx::accumulator, 16, 16, 16, float> pacc[2];
        wx::fill_fragment(pacc[0], 0.0f);
        wx::fill_fragment(pacc[1], 0.0f);
        #pragma unroll
        for (int kk = 0; kk < 4; kk++) {
            wx::fragment<wx::matrix_a, 16, 16, 16, __nv_bfloat16, wx::row_major> apf;
            wx::load_matrix_sync(apf, pp + (wr * 16) * 72 + kk * 16, 72);
            #pragma unroll
            for (int a = 0; a < 2; a++) {
                #pragma unroll
                for (int tv = 0; tv < 2; tv++) {
                    wx::fragment<wx::matrix_b, 16, 16, 16, __nv_bfloat16, wx::row_major> bfr;
                    wx::load_matrix_sync(bfr,
                        vp + tv * 4608 + (kk * 16) * 72 + wc * 32 + a * 16, 72);
                    wx::mma_sync(pacc[a], apf, bfr, pacc[a]);
                }
            }
        }
        #pragma unroll
        for (int a = 0; a < 2; a++)
            wx::store_matrix_sync(od + (wr * 16) * 72 + wc * 32 + a * 16, pacc[a], 72,
                                  wx::mem_row_major);
        __syncthreads();   // S5

        #pragma unroll
        for (int i = 0; i < 4; i++)
            #pragma unroll
            for (int d = 0; d < 4; d++)
                o[i][d] += od[(i0 + i) * 72 + cj + d];
    }

    #pragma unroll
    for (int i = 0; i < 4; i++) {
        float inv = 1.0f / l_i[i];
        float4 w = make_float4(o[i][0] * inv, o[i][1] * inv, o[i][2] * inv, o[i][3] * inv);
        *(float4*)(g_ctx + rowbase + (size_t)(q0 + i0 + i) * HID + cj) = w;
    }
}

// ------------------------- out_scale ---------------------------------------
__global__ void k_out_scale(const float* __restrict__ hss, float* __restrict__ out, int out_size) {
    if (out_size >= MROWS * HID + 1) {
        out[MROWS * HID] = (hss[0] * g_scale[2]) * g_scale[3];
    }
}

// ------------------------- launch ------------------------------------------
extern "C" void kernel_launch(void* const* d_in, const int* in_sizes, int n_in,
                              void* d_out, int out_size) {
    const float* hs  = (const float*)d_in[0];
    const float* hss = (const float*)d_in[1];
    const int*   pos = (const int*)d_in[2];
    const float* wq  = (const float*)d_in[3];
    const float* wk  = (const float*)d_in[4];
    const float* wv  = (const float*)d_in[5];
    const float* wo  = (const float*)d_in[6];
    float* out = (float*)d_out;

    __nv_bfloat16 *p_wb, *p_pl;
    float *p_qkv, *p_ctx;
    cudaGetSymbolAddress((void**)&p_wb,  g_wb);
    cudaGetSymbolAddress((void**)&p_pl,  g_pl);
    cudaGetSymbolAddress((void**)&p_qkv, g_qkv);
    cudaGetSymbolAddress((void**)&p_ctx, g_ctx);

    float* qf = p_qkv + 0 * PLANE;
    float* kf = p_qkv + 1 * PLANE;
    float* vf = p_qkv + 2 * PLANE;

    cudaFuncSetAttribute(k_attn, cudaFuncAttributeMaxDynamicSharedMemorySize, SMEM_ATTN);

    k_abssum<<<dim3(64, 4), 256>>>(wq, wk, wv, wo);
    k_split<<<(MROWS * HID / 4 + 255) / 256, 256>>>(hs);
    k_quant<<<dim3(64, 4), 256>>>(wq, wk, wv, wo);

    dim3 gproj(HID / 128, MROWS / 128);
    k_bgemm3<<<gproj, 256>>>(p_pl, p_wb + 0 * (size_t)WELEM, qf);
    k_bgemm3<<<gproj, 256>>>(p_pl, p_wb + 1 * (size_t)WELEM, kf);
    k_bgemm2<<<gproj, 256>>>(p_pl, p_wb + 2 * (size_t)WELEM, vf);

    k_trig<<<(Ssz * 32 + 255) / 256, 256>>>();
    k_rope<<<(MROWS * NH * 32 + 255) / 256, 256>>>(pos);
    k_vsplit<<<(MROWS * HID + 255) / 256, 256>>>();

    k_attn<<<dim3(Ssz / 64, Bsz * NH), 256, SMEM_ATTN>>>();

    k_split<<<(MROWS * HID / 4 + 255) / 256, 256>>>(p_ctx);
    k_bgemm2<<<gproj, 256>>>(p_pl, p_wb + 3 * (size_t)WELEM, out);

    k_out_scale<<<1, 1>>>(hss, out, out_size);
}

// round 16
// speedup vs baseline: 1.4182x; 1.0123x over previous
#include <cuda_runtime.h>
#include <cuda_bf16.h>
#include <cuda_pipeline.h>
#include <mma.h>
#include <math.h>

// ---------------------------------------------------------------------------
// BitNetAttention: B=2, S=2048, HID=1024, NH=16, HD=64
// Projections AND attention (scores + P*V) on bf16 tensor cores via wmma.
// Exact multi-plane bf16 splits keep everything equal to fp32 up to
// accumulation order. Softmax fp32; P single-plane bf16.
// Projections: cp.async 3-stage pipelines with DYNAMIC shared memory
// (3 stages exceed the 48KB static limit). (No inline asm / template decls /
// uint32_t -- pipeline rewriter constraints.)
// ---------------------------------------------------------------------------

#define Bsz   2
#define Ssz   2048
#define HID   1024
#define NH    16
#define HD    64
#define MROWS (Bsz * Ssz)
#define WELEM (HID * HID)
#define PLANE ((size_t)MROWS * HID)
#define SMEM_ATTN 92160
#define SMEM_G3 73728
#define SMEM_G2 55296
#define STG 3072   // halves per (stage,buffer) = 128*24

namespace wx = nvcuda::wmma;

__device__ double g_part[4][64];
__device__ float  g_scale[4];
__device__ __nv_bfloat16 g_wb[4 * WELEM];
__device__ __nv_bfloat16 g_pl[3 * MROWS * HID];
__device__ __nv_bfloat16 g_qpl[3 * MROWS * HID];
__device__ __nv_bfloat16 g_kpl[3 * MROWS * HID];
__device__ __nv_bfloat16 g_vpl[2 * MROWS * HID];
__device__ float  g_qkv[3 * MROWS * HID];
__device__ float  g_ctx[MROWS * HID];
__device__ float  g_cos[Ssz * 32];
__device__ float  g_sin[Ssz * 32];

// ------------------------- abssum partials ---------------------------------
__global__ __launch_bounds__(256) void k_abssum(const float* __restrict__ w0,
                                                const float* __restrict__ w1,
                                                const float* __restrict__ w2,
                                                const float* __restrict__ w3) {
    const int y = blockIdx.y;
    const float* w = (y == 0) ? w0 : (y == 1) ? w1 : (y == 2) ? w2 : w3;
    float acc = 0.f;
    const int n4 = WELEM / 4;
    for (int i = blockIdx.x * blockDim.x + threadIdx.x; i < n4; i += gridDim.x * blockDim.x) {
        float4 v = ((const float4*)w)[i];
        acc += fabsf(v.x) + fabsf(v.y) + fabsf(v.z) + fabsf(v.w);
    }
    for (int o = 16; o; o >>= 1) acc += __shfl_xor_sync(0xffffffffu, acc, o);
    __shared__ float red[8];
    if ((threadIdx.x & 31) == 0) red[threadIdx.x >> 5] = acc;
    __syncthreads();
    if (threadIdx.x < 8) {
        acc = red[threadIdx.x];
        for (int o = 4; o; o >>= 1) acc += __shfl_xor_sync(0xffu, acc, o);
        if (threadIdx.x == 0) g_part[y][blockIdx.x] = (double)acc;
    }
}

// exact 3-plane split of fp32 into bf16 planes
__global__ __launch_bounds__(256) void k_split(const float* __restrict__ x) {
    int i = blockIdx.x * blockDim.x + threadIdx.x;
    if (i >= (MROWS * HID) / 4) return;
    float4 v = ((const float4*)x)[i];
    float xs[4];
    xs[0] = v.x; xs[1] = v.y; xs[2] = v.z; xs[3] = v.w;
    unsigned int w0[2], w1[2], w2[2];
    #pragma unroll
    for (int pair = 0; pair < 2; pair++) {
        unsigned int a0 = 0, a1 = 0, a2 = 0;
        #pragma unroll
        for (int e = 0; e < 2; e++) {
            float xv = xs[pair * 2 + e];
            __nv_bfloat16 h0 = __float2bfloat16_rn(xv);
            float r1 = __fsub_rn(xv, __bfloat162float(h0));
            __nv_bfloat16 h1 = __float2bfloat16_rn(r1);
            float r2 = __fsub_rn(r1, __bfloat162float(h1));
            __nv_bfloat16 h2 = __float2bfloat16_rn(r2);
            a0 |= (unsigned int)__bfloat16_as_ushort(h0) << (16 * e);
            a1 |= (unsigned int)__bfloat16_as_ushort(h1) << (16 * e);
            a2 |= (unsigned int)__bfloat16_as_ushort(h2) << (16 * e);
        }
        w0[pair] = a0; w1[pair] = a1; w2[pair] = a2;
    }
    ((uint2*)(g_pl + 0 * PLANE))[i] = make_uint2(w0[0], w0[1]);
    ((uint2*)(g_pl + 1 * PLANE))[i] = make_uint2(w1[0], w1[1]);
    ((uint2*)(g_pl + 2 * PLANE))[i] = make_uint2(w2[0], w2[1]);
}

// quantize; absmean scale reduced from partials at block start
__global__ __launch_bounds__(256) void k_quant(const float* __restrict__ w0,
                                               const float* __restrict__ w1,
                                               const float* __restrict__ w2,
                                               const float* __restrict__ w3) {
    const int y = blockIdx.y;
    const float* w = (y == 0) ? w0 : (y == 1) ? w1 : (y == 2) ? w2 : w3;
    __nv_bfloat16* q = g_wb + (size_t)y * WELEM;
    __shared__ float s_sc;
    if (threadIdx.x < 32) {
        double d = g_part[y][threadIdx.x] + g_part[y][threadIdx.x + 32];
        for (int o = 16; o; o >>= 1) d += __shfl_xor_sync(0xffffffffu, d, o);
        if (threadIdx.x == 0) {
            float m = (float)(d * (1.0 / (double)WELEM)) + 1e-5f;
            s_sc = m;
            g_scale[y] = m;
        }
    }
    __syncthreads();
    const float sc = s_sc;
    const int n4 = WELEM / 4;
    for (int i = blockIdx.x * blockDim.x + threadIdx.x; i < n4; i += gridDim.x * blockDim.x) {
        float4 v = ((const float4*)w)[i];
        float r0 = fminf(1.f, fmaxf(-1.f, rintf(__fdiv_rn(v.x, sc))));
        float r1 = fminf(1.f, fmaxf(-1.f, rintf(__fdiv_rn(v.y, sc))));
        float r2 = fminf(1.f, fmaxf(-1.f, rintf(__fdiv_rn(v.z, sc))));
        float r3 = fminf(1.f, fmaxf(-1.f, rintf(__fdiv_rn(v.w, sc))));
        unsigned int lo = ((unsigned int)__bfloat16_as_ushort(__float2bfloat16_rn(r1)) << 16)
                        | (unsigned int)__bfloat16_as_ushort(__float2bfloat16_rn(r0));
        unsigned int hi = ((unsigned int)__bfloat16_as_ushort(__float2bfloat16_rn(r3)) << 16)
                        | (unsigned int)__bfloat16_as_ushort(__float2bfloat16_rn(r2));
        ((uint2*)q)[i] = make_uint2(lo, hi);
    }
}

// ------------------------- wmma bf16 GEMM, 3 planes, cp.async ---------------
// dynamic smem: 3 stages x 4 buffers x 128*24 halves
__global__ __launch_bounds__(256) void k_bgemm3(const __nv_bfloat16* __restrict__ A,
                                                const __nv_bfloat16* __restrict__ B,
                                                float* __restrict__ C) {
    extern __shared__ __align__(16) __nv_bfloat16 smg[];
    const int t = threadIdx.x;
    const int wid = t >> 5;
    const int wm = (wid >> 1) * 32;
    const int wn = (wid & 1) * 64;
    const int lrow = t >> 1;
    const int lcol = (t & 1) * 8;
    const __nv_bfloat16* ag = A + ((size_t)blockIdx.y * 128 + lrow) * HID + lcol;
    const __nv_bfloat16* bg = B + ((size_t)blockIdx.x * 128 + lrow) * HID + lcol;
    const int soff = lrow * 24 + lcol;

    wx::fragment<wx::accumulator, 16, 16, 16, float> acc[2][4];
    #pragma unroll
    for (int i = 0; i < 2; i++)
        #pragma unroll
        for (int j = 0; j < 4; j++)
            wx::fill_fragment(acc[i][j], 0.0f);

    #pragma unroll
    for (int s = 0; s < 2; s++) {
        const int k0 = s * 16;
        __nv_bfloat16* st = smg + s * 4 * STG;
        __pipeline_memcpy_async(st + 0 * STG + soff, ag + 0 * PLANE + k0, 16);
        __pipeline_memcpy_async(st + 1 * STG + soff, ag + 1 * PLANE + k0, 16);
        __pipeline_memcpy_async(st + 2 * STG + soff, ag + 2 * PLANE + k0, 16);
        __pipeline_memcpy_async(st + 3 * STG + soff, bg + k0, 16);
        __pipeline_commit();
    }

    #pragma unroll 1
    for (int it = 0; it < 64; ++it) {
        __pipeline_wait_prior(1);
        __syncthreads();
        __nv_bfloat16* cs = smg + (it % 3) * 4 * STG;
        if (it + 2 < 64) {
            const int k0 = (it + 2) * 16;
            __nv_bfloat16* st = smg + ((it + 2) % 3) * 4 * STG;
            __pipeline_memcpy_async(st + 0 * STG + soff, ag + 0 * PLANE + k0, 16);
            __pipeline_memcpy_async(st + 1 * STG + soff, ag + 1 * PLANE + k0, 16);
            __pipeline_memcpy_async(st + 2 * STG + soff, ag + 2 * PLANE + k0, 16);
            __pipeline_memcpy_async(st + 3 * STG + soff, bg + k0, 16);
        }
        __pipeline_commit();

        wx::fragment<wx::matrix_b, 16, 16, 16, __nv_bfloat16, wx::col_major> bf[4];
        #pragma unroll
        for (int j = 0; j < 4; j++)
            wx::load_matrix_sync(bf[j], cs + 3 * STG + (wn + 16 * j) * 24, 24);
        #pragma unroll
        for (int s = 0; s < 3; s++) {
            wx::fragment<wx::matrix_a, 16, 16, 16, __nv_bfloat16, wx::row_major> af[2];
            wx::load_matrix_sync(af[0], cs + s * STG + (wm) * 24, 24);
            wx::load_matrix_sync(af[1], cs + s * STG + (wm + 16) * 24, 24);
            #pragma unroll
            for (int i = 0; i < 2; i++)
                #pragma unroll
                for (int j = 0; j < 4; j++)
                    wx::mma_sync(acc[i][j], af[i], bf[j], acc[i][j]);
        }
    }

    #pragma unroll
    for (int i = 0; i < 2; i++)
        #pragma unroll
        for (int j = 0; j < 4; j++) {
            float* cp = C + ((size_t)blockIdx.y * 128 + wm + 16 * i) * HID
                          + blockIdx.x * 128 + wn + 16 * j;
            wx::store_matrix_sync(cp, acc[i][j], HID, wx::mem_row_major);
        }
}

// Same with 2 planes (V and O projections), cp.async, dynamic smem.
__global__ __launch_bounds__(256) void k_bgemm2(const __nv_bfloat16* __restrict__ A,
                                                const __nv_bfloat16* __restrict__ B,
                                                float* __restrict__ C) {
    extern __shared__ __align__(16) __nv_bfloat16 smg[];
    const int t = threadIdx.x;
    const int wid = t >> 5;
    const int wm = (wid >> 1) * 32;
    const int wn = (wid & 1) * 64;
    const int lrow = t >> 1;
    const int lcol = (t & 1) * 8;
    const __nv_bfloat16* ag = A + ((size_t)blockIdx.y * 128 + lrow) * HID + lcol;
    const __nv_bfloat16* bg = B + ((size_t)blockIdx.x * 128 + lrow) * HID + lcol;
    const int soff = lrow * 24 + lcol;

    wx::fragment<wx::accumulator, 16, 16, 16, float> acc[2][4];
    #pragma unroll
    for (int i = 0; i < 2; i++)
        #pragma unroll
        for (int j = 0; j < 4; j++)
            wx::fill_fragment(acc[i][j], 0.0f);

    #pragma unroll
    for (int s = 0; s < 2; s++) {
        const int k0 = s * 16;
        __nv_bfloat16* st = smg + s * 3 * STG;
        __pipeline_memcpy_async(st + 0 * STG + soff, ag + 0 * PLANE + k0, 16);
        __pipeline_memcpy_async(st + 1 * STG + soff, ag + 1 * PLANE + k0, 16);
        __pipeline_memcpy_async(st + 2 * STG + soff, bg + k0, 16);
        __pipeline_commit();
    }

    #pragma unroll 1
    for (int it = 0; it < 64; ++it) {
        __pipeline_wait_prior(1);
        __syncthreads();
        __nv_bfloat16* cs = smg + (it % 3) * 3 * STG;
        if (it + 2 < 64) {
            const int k0 = (it + 2) * 16;
            __nv_bfloat16* st = smg + ((it + 2) % 3) * 3 * STG;
            __pipeline_memcpy_async(st + 0 * STG + soff, ag + 0 * PLANE + k0, 16);
            __pipeline_memcpy_async(st + 1 * STG + soff, ag + 1 * PLANE + k0, 16);
            __pipeline_memcpy_async(st + 2 * STG + soff, bg + k0, 16);
        }
        __pipeline_commit();

        wx::fragment<wx::matrix_b, 16, 16, 16, __nv_bfloat16, wx::col_major> bf[4];
        #pragma unroll
        for (int j = 0; j < 4; j++)
            wx::load_matrix_sync(bf[j], cs + 2 * STG + (wn + 16 * j) * 24, 24);
        #pragma unroll
        for (int s = 0; s < 2; s++) {
            wx::fragment<wx::matrix_a, 16, 16, 16, __nv_bfloat16, wx::row_major> af[2];
            wx::load_matrix_sync(af[0], cs + s * STG + (wm) * 24, 24);
            wx::load_matrix_sync(af[1], cs + s * STG + (wm + 16) * 24, 24);
            #pragma unroll
            for (int i = 0; i < 2; i++)
                #pragma unroll
                for (int j = 0; j < 4; j++)
                    wx::mma_sync(acc[i][j], af[i], bf[j], acc[i][j]);
        }
    }

    #pragma unroll
    for (int i = 0; i < 2; i++)
        #pragma unroll
        for (int j = 0; j < 4; j++) {
            float* cp = C + ((size_t)blockIdx.y * 128 + wm + 16 * i) * HID
                          + blockIdx.x * 128 + wn + 16 * j;
            wx::store_matrix_sync(cp, acc[i][j], HID, wx::mem_row_major);
        }
}

// ------------------------- trig table --------------------------------------
__global__ __launch_bounds__(256) void k_trig() {
    int idx = blockIdx.x * blockDim.x + threadIdx.x;
    if (idx >= Ssz * 32) return;
    int pos = idx >> 5;
    int d2  = idx & 31;
    float e = (float)(2 * d2) / 64.0f;
    float t = (float)pow(10000.0, (double)e);
    float invf = __frcp_rn(t);
    float f = __fmul_rn((float)pos, invf);
    double sd, cd;
    sincos((double)f, &sd, &cd);
    g_cos[idx] = (float)cd;
    g_sin[idx] = (float)sd;
}

// ------------------------- RoPE + exact 3-plane split of q,k ----------------
__global__ __launch_bounds__(256) void k_rope(const int* __restrict__ pos_ids) {
    int idx = blockIdx.x * blockDim.x + threadIdx.x;
    if (idx >= MROWS * NH * 32) return;
    int m  = idx >> 9;
    int hp = idx & 511;
    int h  = hp >> 5;
    int d2 = hp & 31;
    int p = pos_ids[m];
    p = (p < 0) ? 0 : ((p >= Ssz) ? Ssz - 1 : p);
    float cs = g_cos[p * 32 + d2];
    float sn = g_sin[p * 32 + d2];
    size_t base = (size_t)m * HID + h * HD + d2;
    float q1 = g_qkv[base], q2 = g_qkv[base + 32];
    float k1 = g_qkv[PLANE + base], k2 = g_qkv[PLANE + base + 32];
    float vals[4];
    vals[0] = q1 * cs - q2 * sn;
    vals[1] = q2 * cs + q1 * sn;
    vals[2] = k1 * cs - k2 * sn;
    vals[3] = k2 * cs + k1 * sn;
    #pragma unroll
    for (int e = 0; e < 4; e++) {
        float xv = vals[e];
        __nv_bfloat16 h0 = __float2bfloat16_rn(xv);
        float r1 = __fsub_rn(xv, __bfloat162float(h0));
        __nv_bfloat16 h1 = __float2bfloat16_rn(r1);
        float r2 = __fsub_rn(r1, __bfloat162float(h1));
        __nv_bfloat16 h2 = __float2bfloat16_rn(r2);
        __nv_bfloat16* dst = (e < 2) ? g_qpl : g_kpl;
        size_t a = base + ((e & 1) ? 32 : 0);
        dst[0 * PLANE + a] = h0;
        dst[1 * PLANE + a] = h1;
        dst[2 * PLANE + a] = h2;
    }
}

// exact 2-plane split of V
__global__ __launch_bounds__(256) void k_vsplit() {
    int i = blockIdx.x * blockDim.x + threadIdx.x;
    if (i >= MROWS * HID) return;
    float xv = g_qkv[2 * PLANE + i];
    __nv_bfloat16 h0 = __float2bfloat16_rn(xv);
    float r1 = __fsub_rn(xv, __bfloat162float(h0));
    __nv_bfloat16 h1 = __float2bfloat16_rn(r1);
    g_vpl[0 * PLANE + i] = h0;
    g_vpl[1 * PLANE + i] = h1;
}

// ------------------------- attention (full wmma) ----------------------------
// Q tile 64, K tile 64. Dynamic smem layout (bytes):
//   qp  3x[64][72] bf16 @ 0      (27648)
//   kp  3x[64][72] bf16 @ 27648  (27648)   <- pp 1x[64][72] bf16 aliases here
//   vp  2x[64][72] bf16 @ 55296  (18432)
//   sc  [64][72] f32    @ 73728  (18432)   <- od aliases here
// total 92160
__global__ __launch_bounds__(256, 2) void k_attn() {
    extern __shared__ __align__(16) char smb[];
    __nv_bfloat16* qp = (__nv_bfloat16*)(smb);
    __nv_bfloat16* kp = (__nv_bfloat16*)(smb + 27648);
    __nv_bfloat16* pp = (__nv_bfloat16*)(smb + 27648);
    __nv_bfloat16* vp = (__nv_bfloat16*)(smb + 55296);
    float* sc = (float*)(smb + 73728);
    float* od = (float*)(smb + 73728);

    const int tid = threadIdx.x;
    const int wid = tid >> 5;
    const int b = blockIdx.y >> 4;
    const int h = blockIdx.y & 15;
    const int q0 = blockIdx.x * 64;
    const size_t rowbase = (size_t)b * Ssz * HID + (size_t)h * HD;

    for (int idx = tid; idx < 64 * 16; idx += 256) {
        int r = idx >> 4;
        int c4 = (idx & 15) * 4;
        size_t g = rowbase + (size_t)(q0 + r) * HID + c4;
        *(uint2*)(qp + 0 * 4608 + r * 72 + c4) = *(const uint2*)(g_qpl + 0 * PLANE + g);
        *(uint2*)(qp + 1 * 4608 + r * 72 + c4) = *(const uint2*)(g_qpl + 1 * PLANE + g);
        *(uint2*)(qp + 2 * 4608 + r * 72 + c4) = *(const uint2*)(g_qpl + 2 * PLANE + g);
    }

    const int ty = tid >> 4, tx = tid & 15;
    const int i0 = ty << 2;
    const int j0 = tx << 2;
    const int cj = tx << 2;
    const int wr = wid >> 1;
    const int wc = wid & 1;

    float m_i[4], l_i[4], o[4][4];
    #pragma unroll
    for (int i = 0; i < 4; i++) {
        m_i[i] = -3.0e38f; l_i[i] = 0.f;
        #pragma unroll
        for (int d = 0; d < 4; d++) o[i][d] = 0.f;
    }

    for (int kt = 0; kt < Ssz; kt += 64) {
        __syncthreads();   // S1
        for (int idx = tid; idx < 64 * 16; idx += 256) {
            int r = idx >> 4;
            int c4 = (idx & 15) * 4;
            size_t g = rowbase + (size_t)(kt + r) * HID + c4;
            *(uint2*)(kp + 0 * 4608 + r * 72 + c4) = *(const uint2*)(g_kpl + 0 * PLANE + g);
            *(uint2*)(kp + 1 * 4608 + r * 72 + c4) = *(const uint2*)(g_kpl + 1 * PLANE + g);
            *(uint2*)(kp + 2 * 4608 + r * 72 + c4) = *(const uint2*)(g_kpl + 2 * PLANE + g);
            *(uint2*)(vp + 0 * 4608 + r * 72 + c4) = *(const uint2*)(g_vpl + 0 * PLANE + g);
            *(uint2*)(vp + 1 * 4608 + r * 72 + c4) = *(const uint2*)(g_vpl + 1 * PLANE + g);
        }
        __syncthreads();   // S2

        wx::fragment<wx::accumulator, 16, 16, 16, float> sacc[2];
        wx::fill_fragment(sacc[0], 0.0f);
        wx::fill_fragment(sacc[1], 0.0f);
        #pragma unroll
        for (int kk = 0; kk < 4; kk++) {
            wx::fragment<wx::matrix_a, 16, 16, 16, __nv_bfloat16, wx::row_major> af[3];
            #pragma unroll
            for (int si = 0; si < 3; si++)
                wx::load_matrix_sync(af[si], qp + si * 4608 + (wr * 16) * 72 + kk * 16, 72);
            #pragma unroll
            for (int a = 0; a < 2; a++) {
                #pragma unroll
                for (int sj = 0; sj < 3; sj++) {
                    wx::fragment<wx::matrix_b, 16, 16, 16, __nv_bfloat16, wx::col_major> bfr;
                    wx::load_matrix_sync(bfr,
                        kp + sj * 4608 + (wc * 32 + a * 16) * 72 + kk * 16, 72);
                    #pragma unroll
                    for (int si = 0; si < 3; si++)
                        if (si + sj <= 2)
                            wx::mma_sync(sacc[a], af[si], bfr, sacc[a]);
                }
            }
        }
        #pragma unroll
        for (int a = 0; a < 2; a++)
            wx::store_matrix_sync(sc + (wr * 16) * 72 + wc * 32 + a * 16, sacc[a], 72,
                                  wx::mem_row_major);
        __syncthreads();   // S3

        #pragma unroll
        for (int i = 0; i < 4; i++) {
            int row = i0 + i;
            float sv0 = sc[row * 72 + j0 + 0] * 0.125f;
            float sv1 = sc[row * 72 + j0 + 1] * 0.125f;
            float sv2 = sc[row * 72 + j0 + 2] * 0.125f;
            float sv3 = sc[row * 72 + j0 + 3] * 0.125f;
            float mx = fmaxf(fmaxf(sv0, sv1), fmaxf(sv2, sv3));
            #pragma unroll
            for (int off = 8; off; off >>= 1)
                mx = fmaxf(mx, __shfl_xor_sync(0xffffffffu, mx, off));
            float mnew = fmaxf(m_i[i], mx);
            float corr = __expf(m_i[i] - mnew);
            float p0 = __expf(sv0 - mnew);
            float p1 = __expf(sv1 - mnew);
            float p2 = __expf(sv2 - mnew);
            float p3 = __expf(sv3 - mnew);
            float rs = p0 + p1 + p2 + p3;
            #pragma unroll
            for (int off = 8; off; off >>= 1)
                rs += __shfl_xor_sync(0xffffffffu, rs, off);
            l_i[i] = l_i[i] * corr + rs;
            m_i[i] = mnew;
            #pragma unroll
            for (int d = 0; d < 4; d++) o[i][d] *= corr;
            unsigned int lo = ((unsigned int)__bfloat16_as_ushort(__float2bfloat16_rn(p1)) << 16)
                            | (unsigned int)__bfloat16_as_ushort(__float2bfloat16_rn(p0));
            unsigned int hi = ((unsigned int)__bfloat16_as_ushort(__float2bfloat16_rn(p3)) << 16)
                            | (unsigned int)__bfloat16_as_ushort(__float2bfloat16_rn(p2));
            *(unsigned int*)(pp + row * 72 + j0)     = lo;
            *(unsigned int*)(pp + row * 72 + j0 + 2) = hi;
        }
        __syncthreads();   // S4

        wx::fragment<wx::accumulator, 16, 16, 16, float> pacc[2];
        wx::fill_fragment(pacc[0], 0.0f);
        wx::fill_fragment(pacc[1], 0.0f);
        #pragma unroll
        for (int kk = 0; kk < 4; kk++) {
            wx::fragment<wx::matrix_a, 16, 16, 16, __nv_bfloat16, wx::row_major> apf;
            wx::load_matrix_sync(apf, pp + (wr * 16) * 72 + kk * 16, 72);
            #pragma unroll
            for (int a = 0; a < 2; a++) {
                #pragma unroll
                for (int tv = 0; tv < 2; tv++) {
                    wx::fragment<wx::matrix_b, 16, 16, 16, __nv_bfloat16, wx::row_major> bfr;
                    wx::load_matrix_sync(bfr,
                        vp + tv * 4608 + (kk * 16) * 72 + wc * 32 + a * 16, 72);
                    wx::mma_sync(pacc[a], apf, bfr, pacc[a]);
                }
            }
        }
        #pragma unroll
        for (int a = 0; a < 2; a++)
            wx::store_matrix_sync(od + (wr * 16) * 72 + wc * 32 + a * 16, pacc[a], 72,
                                  wx::mem_row_major);
        __syncthreads();   // S5

        #pragma unroll
        for (int i = 0; i < 4; i++)
            #pragma unroll
            for (int d = 0; d < 4; d++)
                o[i][d] += od[(i0 + i) * 72 + cj + d];
    }

    #pragma unroll
    for (int i = 0; i < 4; i++) {
        float inv = 1.0f / l_i[i];
        float4 w = make_float4(o[i][0] * inv, o[i][1] * inv, o[i][2] * inv, o[i][3] * inv);
        *(float4*)(g_ctx + rowbase + (size_t)(q0 + i0 + i) * HID + cj) = w;
    }
}

// ------------------------- out_scale ---------------------------------------
__global__ void k_out_scale(const float* __restrict__ hss, float* __restrict__ out, int out_size) {
    if (out_size >= MROWS * HID + 1) {
        out[MROWS * HID] = (hss[0] * g_scale[2]) * g_scale[3];
    }
}

// ------------------------- launch ------------------------------------------
extern "C" void kernel_launch(void* const* d_in, const int* in_sizes, int n_in,
                              void* d_out, int out_size) {
    const float* hs  = (const float*)d_in[0];
    const float* hss = (const float*)d_in[1];
    const int*   pos = (const int*)d_in[2];
    const float* wq  = (const float*)d_in[3];
    const float* wk  = (const float*)d_in[4];
    const float* wv  = (const float*)d_in[5];
    const float* wo  = (const float*)d_in[6];
    float* out = (float*)d_out;

    __nv_bfloat16 *p_wb, *p_pl;
    float *p_qkv, *p_ctx;
    cudaGetSymbolAddress((void**)&p_wb,  g_wb);
    cudaGetSymbolAddress((void**)&p_pl,  g_pl);
    cudaGetSymbolAddress((void**)&p_qkv, g_qkv);
    cudaGetSymbolAddress((void**)&p_ctx, g_ctx);

    float* qf = p_qkv + 0 * PLANE;
    float* kf = p_qkv + 1 * PLANE;
    float* vf = p_qkv + 2 * PLANE;

    cudaFuncSetAttribute(k_attn, cudaFuncAttributeMaxDynamicSharedMemorySize, SMEM_ATTN);
    cudaFuncSetAttribute(k_bgemm3, cudaFuncAttributeMaxDynamicSharedMemorySize, SMEM_G3);
    cudaFuncSetAttribute(k_bgemm2, cudaFuncAttributeMaxDynamicSharedMemorySize, SMEM_G2);

    k_abssum<<<dim3(64, 4), 256>>>(wq, wk, wv, wo);
    k_split<<<(MROWS * HID / 4 + 255) / 256, 256>>>(hs);
    k_quant<<<dim3(64, 4), 256>>>(wq, wk, wv, wo);

    dim3 gproj(HID / 128, MROWS / 128);
    k_bgemm3<<<gproj, 256, SMEM_G3>>>(p_pl, p_wb + 0 * (size_t)WELEM, qf);
    k_bgemm3<<<gproj, 256, SMEM_G3>>>(p_pl, p_wb + 1 * (size_t)WELEM, kf);
    k_bgemm2<<<gproj, 256, SMEM_G2>>>(p_pl, p_wb + 2 * (size_t)WELEM, vf);

    k_trig<<<(Ssz * 32 + 255) / 256, 256>>>();
    k_rope<<<(MROWS * NH * 32 + 255) / 256, 256>>>(pos);
    k_vsplit<<<(MROWS * HID + 255) / 256, 256>>>();

    k_attn<<<dim3(Ssz / 64, Bsz * NH), 256, SMEM_ATTN>>>();

    k_split<<<(MROWS * HID / 4 + 255) / 256, 256>>>(p_ctx);
    k_bgemm2<<<gproj, 256, SMEM_G2>>>(p_pl, p_wb + 3 * (size_t)WELEM, out);

    k_out_scale<<<1, 1>>>(hss, out, out_size);
}